// round 9
// baseline (speedup 1.0000x reference)
#include <cuda_runtime.h>

#define HID 50
#define NPTS 8192
#define NPARA 5000
#define WARPS_PER_BLOCK 8
#define THREADS (WARPS_PER_BLOCK * 32)
#define NBLOCKS 444                     // exactly 3 CTAs per SM on 148 SMs
#define BASE_WARPS (NBLOCKS * WARPS_PER_BLOCK)   // 3552
#define NTASKS (NPTS / 2)               // 4096 two-point tasks

// shared layout (floats)
#define OFF_WIN 0
#define OFF_BIN 150
#define OFF_WP  200                     // 4 layers x 50k x 32 float2 = 12800 floats
#define OFF_BHP 13000                   // 4 layers x 32 float2 = 256 floats
#define OFF_WO  13256
#define OFF_BO  13356
#define OFF_STATE 13360                 // 16B aligned (13360*4 % 16 == 0)
// per warp: stA0 50x4 + stA1 50x4 + stBB 50x4 = 600 floats
#define STATE_STRIDE 600
#define OFF_OUT16 (OFF_STATE + WARPS_PER_BLOCK * STATE_STRIDE)  // 18160
#define OFF_PART (OFF_OUT16 + WARPS_PER_BLOCK * 16)             // 18288
#define SMEM_FLOATS (OFF_PART + WARPS_PER_BLOCK * 12)           // 18384
#define SMEM_BYTES (SMEM_FLOATS * 4)    // 73536 B -> 3 CTAs/SM (220.6KB/SM)

__device__ double g_sums[6];            // zero-initialized at load; reset after finalize

// tanh(z) and sech^2(z): r = 1/(e^{2z}+1); h = 1-2r; 1-h^2 = 4r(1-r)
__device__ __forceinline__ void tanh_s(float z, float& h, float& s) {
    float e = __expf(2.0f * z);
    float r = __fdividef(1.0f, e + 1.0f);
    h = 1.0f - 2.0f * r;
    s = 4.0f * r * (1.0f - r);
}

__device__ __forceinline__ void chain6(float z, float zx, float zxx, float zy,
                                       float zyy, float zt,
                                       float& h, float& d0, float& dd0,
                                       float& d1, float& dd1, float& d2) {
    float s; tanh_s(z, h, s);
    d0  = s * zx;
    dd0 = fmaf(-2.0f * h * d0, zx, s * zxx);
    d1  = s * zy;
    dd1 = fmaf(-2.0f * h * d1, zy, s * zyy);
    d2  = s * zt;
}

__global__ void __launch_bounds__(THREADS, 3) pinn_kernel(
    const float* __restrict__ x,
    const float* __restrict__ W_in, const float* __restrict__ b_in,
    const float* __restrict__ W_hid, const float* __restrict__ b_hid,
    const float* __restrict__ W_out, const float* __restrict__ b_out)
{
    extern __shared__ float sm[];
    const int tid = threadIdx.x;

    // paired hidden weights: Wp[l][k][j] = {W[l][k][j], j+32<50 ? W[l][k][j+32] : 0}
    for (int idx = tid; idx < 6400; idx += THREADS) {
        int l = idx / 1600, rem = idx % 1600, k = rem >> 5, j = rem & 31;
        float wa = W_hid[l * 2500 + k * 50 + j];
        float wb = (j + 32 < HID) ? W_hid[l * 2500 + k * 50 + j + 32] : 0.0f;
        ((float2*)(sm + OFF_WP))[idx] = make_float2(wa, wb);
    }
    for (int idx = tid; idx < 128; idx += THREADS) {
        int l = idx >> 5, j = idx & 31;
        float ba = b_hid[l * 50 + j];
        float bb = (j + 32 < HID) ? b_hid[l * 50 + j + 32] : 0.0f;
        ((float2*)(sm + OFF_BHP))[idx] = make_float2(ba, bb);
    }
    for (int i = tid; i < 150; i += THREADS) sm[OFF_WIN + i] = W_in[i];
    for (int i = tid; i < 50;  i += THREADS) sm[OFF_BIN + i] = b_in[i];
    for (int i = tid; i < 100; i += THREADS) sm[OFF_WO  + i] = W_out[i];
    if (tid < 2) sm[OFF_BO + tid] = b_out[tid];
    for (int i = tid; i < WARPS_PER_BLOCK * 12; i += THREADS)
        sm[OFF_PART + i] = 0.0f;
    __syncthreads();

    const int warp = tid >> 5;
    const int lane = tid & 31;
    const int bid = blockIdx.x;
    float* stA0 = sm + OFF_STATE + warp * STATE_STRIDE;  // pt0: 50 x {h,dx,dxx,dy}
    float* stA1 = stA0 + 200;                            // pt1: 50 x {h,dx,dxx,dy}
    float* stBB = stA0 + 400;                            // 50 x {dyy0,dt0,dyy1,dt1}

    const int j1 = lane;
    const int j2 = lane + 32;
    const bool has2 = (j2 < HID);

    // ---- task schedule: everyone gets gwarp; 544 extras spread over SMSPs.
    // Co-resident CTAs on an SM are bids {i, i+148, i+296}; (bid>>2)&7 rotates
    // the doubled warp across distinct SMSPs on each SM (offsets 5,2 mod 8).
    const int gwarp = bid * WARPS_PER_BLOCK + warp;
    const int dw = (bid >> 2) & 7;
    int extra = -1;
    if (warp == dw)                          extra = BASE_WARPS + bid;          // 3552..3995
    else if (bid < 100 && warp == ((dw + 1) & 7)) extra = BASE_WARPS + 444 + bid; // 3996..4095

    for (int rep = 0; rep < 2; rep++) {
        int task = rep ? extra : gwarp;
        if (task < 0) break;
        const int p0 = task * 2;
        const float x00 = x[p0 * 3 + 0], x01 = x[p0 * 3 + 1], x02 = x[p0 * 3 + 2];
        const float x10 = x[p0 * 3 + 3], x11 = x[p0 * 3 + 4], x12 = x[p0 * 3 + 5];
        __syncwarp();   // prior task's epilogue reads done before overwrite

        // ---- input layer for both points
        #pragma unroll
        for (int o = 0; o < 2; o++) {
            int j = lane + 32 * o;
            if (j < HID) {
                float w0 = sm[OFF_WIN + j];
                float w1 = sm[OFF_WIN + 50 + j];
                float w2 = sm[OFF_WIN + 100 + j];
                float bj = sm[OFF_BIN + j];
                float z0 = bj + x00 * w0 + x01 * w1 + x02 * w2;
                float z1 = bj + x10 * w0 + x11 * w1 + x12 * w2;
                float h0, s0; tanh_s(z0, h0, s0);
                float h1, s1; tanh_s(z1, h1, s1);
                float d00 = s0 * w0, dd00 = -2.0f * h0 * d00 * w0;
                float d10 = s0 * w1, dd10 = -2.0f * h0 * d10 * w1;
                float d20 = s0 * w2;
                float d01 = s1 * w0, dd01 = -2.0f * h1 * d01 * w0;
                float d11 = s1 * w1, dd11 = -2.0f * h1 * d11 * w1;
                float d21 = s1 * w2;
                ((float4*)stA0)[j] = make_float4(h0, d00, dd00, d10);
                ((float4*)stA1)[j] = make_float4(h1, d01, dd01, d11);
                ((float4*)stBB)[j] = make_float4(dd10, d20, dd11, d21);
            }
        }
        __syncwarp();

        // ---- 4 hidden layers: 4 LDS + 24 FMA per k
        for (int l = 0; l < 4; l++) {
            const float2* Wp = (const float2*)(sm + OFF_WP) + l * 1600;
            float2 bb = ((const float2*)(sm + OFF_BHP))[l * 32 + lane];

            float q000 = bb.x, q010 = 0.f, q020 = 0.f, q030 = 0.f, q040 = 0.f, q050 = 0.f;
            float q001 = bb.y, q011 = 0.f, q021 = 0.f, q031 = 0.f, q041 = 0.f, q051 = 0.f;
            float q100 = bb.x, q110 = 0.f, q120 = 0.f, q130 = 0.f, q140 = 0.f, q150 = 0.f;
            float q101 = bb.y, q111 = 0.f, q121 = 0.f, q131 = 0.f, q141 = 0.f, q151 = 0.f;

            #pragma unroll
            for (int k = 0; k < HID; k++) {
                float2 w  = Wp[k * 32 + lane];           // LDS.64, conflict-free
                float4 A0 = ((const float4*)stA0)[k];    // broadcast
                float4 A1 = ((const float4*)stA1)[k];    // broadcast
                float4 BB = ((const float4*)stBB)[k];    // broadcast
                q000 = fmaf(A0.x, w.x, q000); q001 = fmaf(A0.x, w.y, q001);
                q010 = fmaf(A0.y, w.x, q010); q011 = fmaf(A0.y, w.y, q011);
                q020 = fmaf(A0.z, w.x, q020); q021 = fmaf(A0.z, w.y, q021);
                q030 = fmaf(A0.w, w.x, q030); q031 = fmaf(A0.w, w.y, q031);
                q040 = fmaf(BB.x, w.x, q040); q041 = fmaf(BB.x, w.y, q041);
                q050 = fmaf(BB.y, w.x, q050); q051 = fmaf(BB.y, w.y, q051);
                q100 = fmaf(A1.x, w.x, q100); q101 = fmaf(A1.x, w.y, q101);
                q110 = fmaf(A1.y, w.x, q110); q111 = fmaf(A1.y, w.y, q111);
                q120 = fmaf(A1.z, w.x, q120); q121 = fmaf(A1.z, w.y, q121);
                q130 = fmaf(A1.w, w.x, q130); q131 = fmaf(A1.w, w.y, q131);
                q140 = fmaf(BB.z, w.x, q140); q141 = fmaf(BB.z, w.y, q141);
                q150 = fmaf(BB.w, w.x, q150); q151 = fmaf(BB.w, w.y, q151);
            }
            __syncwarp();   // all reads of old state done before overwrite
            {
                float h0,d00,dd00,d10,dd10,d20, h1,d01,dd01,d11,dd11,d21;
                chain6(q000,q010,q020,q030,q040,q050, h0,d00,dd00,d10,dd10,d20);
                chain6(q100,q110,q120,q130,q140,q150, h1,d01,dd01,d11,dd11,d21);
                ((float4*)stA0)[j1] = make_float4(h0, d00, dd00, d10);
                ((float4*)stA1)[j1] = make_float4(h1, d01, dd01, d11);
                ((float4*)stBB)[j1] = make_float4(dd10, d20, dd11, d21);
            }
            if (has2) {
                float h0,d00,dd00,d10,dd10,d20, h1,d01,dd01,d11,dd11,d21;
                chain6(q001,q011,q021,q031,q041,q051, h0,d00,dd00,d10,dd10,d20);
                chain6(q101,q111,q121,q131,q141,q151, h1,d01,dd01,d11,dd11,d21);
                ((float4*)stA0)[j2] = make_float4(h0, d00, dd00, d10);
                ((float4*)stA1)[j2] = make_float4(h1, d01, dd01, d11);
                ((float4*)stBB)[j2] = make_float4(dd10, d20, dd11, d21);
            }
            __syncwarp();
        }

        // ---- output layer: lanes 0-7 pt0, 8-15 pt1; channels {val,dxx,dyy,dt} x {u,v}
        if (lane < 16) {
            int pt = lane >> 3;
            int l8 = lane & 7;
            int cidx = l8 >> 1;              // 0=val, 1=dxx, 2=dyy, 3=dt
            int o = l8 & 1;
            const float* base; int off;
            if (cidx < 2) { base = pt ? stA1 : stA0; off = 2 * cidx; }
            else          { base = stBB; off = ((cidx == 2) ? 0 : 1) + 2 * pt; }
            float acc0 = (cidx == 0) ? sm[OFF_BO + o] : 0.0f;
            float acc1 = 0.0f;
            #pragma unroll
            for (int k = 0; k < HID; k += 2) {
                acc0 = fmaf(base[k * 4 + off],       sm[OFF_WO + k * 2 + o],       acc0);
                acc1 = fmaf(base[(k + 1) * 4 + off], sm[OFF_WO + (k + 1) * 2 + o], acc1);
            }
            sm[OFF_OUT16 + warp * 16 + lane] = acc0 + acc1;
        }
        __syncwarp();

        if (lane < 2) {                      // lane 0 -> pt0, lane 1 -> pt1
            const float* o8 = sm + OFF_OUT16 + warp * 16 + lane * 8;
            float u   = o8[0], v   = o8[1];
            float uxx = o8[2], vxx = o8[3];
            float uyy = o8[4], vyy = o8[5];
            float ut  = o8[6], vt  = o8[7];
            float Q  = u * u + v * v;
            float A1 = vt - 0.5f * uxx - 0.5f * vyy - Q * u + v;
            float A2 = ut + 0.5f * vxx - 0.5f * uyy + Q * v + u;
            float B1 = uyy, B2 = vyy;
            float C1 = Q * v, C2 = Q * u;
            float* pp = sm + OFF_PART + (warp * 2 + lane) * 6;
            pp[0] += A1 * A1 + A2 * A2;
            pp[1] += B1 * B1 + B2 * B2;
            pp[2] += C1 * C1 + C2 * C2;
            pp[3] += A2 * B2 - A1 * B1;
            pp[4] += A1 * C1 + A2 * C2;
            pp[5] += B1 * C1 - B2 * C2;
        }
    }
    __syncthreads();

    if (tid < 6) {
        double s = 0.0;
        #pragma unroll
        for (int w = 0; w < WARPS_PER_BLOCK * 2; w++)
            s += (double)sm[OFF_PART + w * 6 + tid];
        atomicAdd(&g_sums[tid], s);
    }
}

__global__ void finalize_kernel(const float* __restrict__ para, float* __restrict__ out) {
    int p = blockIdx.x * blockDim.x + threadIdx.x;
    if (p < NPARA) {
        double a = (double)para[p * 3 + 0];
        double c = (double)para[p * 3 + 2];
        double r = g_sums[0]
                 + 0.25 * a * a * g_sums[1]
                 + c * c * g_sums[2]
                 + a * g_sums[3]
                 - 2.0 * c * g_sums[4]
                 + a * c * g_sums[5];
        out[p] = (float)(r * (1.0 / (double)NPTS));
    }
}

__global__ void reset_kernel() {
    if (threadIdx.x < 6) g_sums[threadIdx.x] = 0.0;
}

extern "C" void kernel_launch(void* const* d_in, const int* in_sizes, int n_in,
                              void* d_out, int out_size) {
    const float* x     = (const float*)d_in[0];
    const float* para  = (const float*)d_in[1];
    const float* W_in  = (const float*)d_in[2];
    const float* b_in  = (const float*)d_in[3];
    const float* W_hid = (const float*)d_in[4];
    const float* b_hid = (const float*)d_in[5];
    const float* W_out = (const float*)d_in[6];
    const float* b_out = (const float*)d_in[7];
    float* out = (float*)d_out;

    cudaFuncSetAttribute(pinn_kernel, cudaFuncAttributeMaxDynamicSharedMemorySize, SMEM_BYTES);
    pinn_kernel<<<NBLOCKS, THREADS, SMEM_BYTES>>>(
        x, W_in, b_in, W_hid, b_hid, W_out, b_out);
    finalize_kernel<<<(NPARA + 255) / 256, 256>>>(para, out);
    reset_kernel<<<1, 32>>>();
}

// round 10
// speedup vs baseline: 1.0286x; 1.0286x over previous
#include <cuda_runtime.h>

#define HID 50
#define NPTS 8192
#define NPARA 5000
#define WARPS_PER_BLOCK 8
#define THREADS (WARPS_PER_BLOCK * 32)
#define NBLOCKS 296                      // exactly 2 CTAs per SM on 148 SMs
#define TOTAL_WARPS (NBLOCKS * WARPS_PER_BLOCK)   // 2368
#define NTASKS (NPTS / 2)                // 4096 two-point tasks

// shared layout (floats)
#define OFF_WIN 0
#define OFF_BIN 150
#define OFF_WH  200
#define OFF_BH  10200
#define OFF_WO  10400
#define OFF_BO  10500
#define OFF_STATE 10504                 // 16B aligned
#define STATE_STRIDE 600                // 2 points x (stA 50x4 + stB 50x2)
#define OFF_OUT16 (OFF_STATE + WARPS_PER_BLOCK * STATE_STRIDE)  // 15304
#define OFF_PART (OFF_OUT16 + WARPS_PER_BLOCK * 16)             // 15432
#define OFF_FLAG (OFF_PART + WARPS_PER_BLOCK * 12)              // 15528
#define SMEM_FLOATS (OFF_FLAG + 4)
#define SMEM_BYTES (SMEM_FLOATS * 4)    // ~62.1 KB

__device__ double g_sums[6];            // zero-init at load; reset by last block
__device__ unsigned int g_ticket;       // zero-init at load; reset by last block

// tanh(z) and sech^2(z): r = 1/(e^{2z}+1); h = 1-2r; 1-h^2 = 4r(1-r)
__device__ __forceinline__ void tanh_s(float z, float& h, float& s) {
    float e = __expf(2.0f * z);
    float r = __fdividef(1.0f, e + 1.0f);
    h = 1.0f - 2.0f * r;
    s = 4.0f * r * (1.0f - r);
}

// tanh chain + split-array state write for one unit of one point
__device__ __forceinline__ void chain_store(float* stA, float* stB, int j,
                                            float z, float zx, float zxx,
                                            float zy, float zyy, float zt) {
    float h, s; tanh_s(z, h, s);
    float d0  = s * zx;
    float dd0 = fmaf(-2.0f * h * d0, zx, s * zxx);
    float d1  = s * zy;
    float dd1 = fmaf(-2.0f * h * d1, zy, s * zyy);
    float d2  = s * zt;
    ((float4*)stA)[j] = make_float4(h, d0, dd0, d1);
    ((float2*)stB)[j] = make_float2(dd1, d2);
}

__global__ void __launch_bounds__(THREADS) pinn_kernel(
    const float* __restrict__ x,
    const float* __restrict__ para,
    const float* __restrict__ W_in, const float* __restrict__ b_in,
    const float* __restrict__ W_hid, const float* __restrict__ b_hid,
    const float* __restrict__ W_out, const float* __restrict__ b_out,
    float* __restrict__ out)
{
    extern __shared__ float sm[];
    const int tid = threadIdx.x;

    for (int i = tid; i < 2500; i += THREADS)
        ((float4*)(sm + OFF_WH))[i] = ((const float4*)W_hid)[i];
    for (int i = tid; i < 150;  i += THREADS) sm[OFF_WIN + i] = W_in[i];
    for (int i = tid; i < 50;   i += THREADS) sm[OFF_BIN + i] = b_in[i];
    for (int i = tid; i < 200;  i += THREADS) sm[OFF_BH  + i] = b_hid[i];
    for (int i = tid; i < 100;  i += THREADS) sm[OFF_WO  + i] = W_out[i];
    if (tid < 2) sm[OFF_BO + tid] = b_out[tid];
    for (int i = tid; i < WARPS_PER_BLOCK * 12; i += THREADS)
        sm[OFF_PART + i] = 0.0f;        // per-warp residual accumulators
    __syncthreads();

    const int warp = tid >> 5;
    const int lane = tid & 31;
    const int bid = blockIdx.x;
    const int gwarp = bid * WARPS_PER_BLOCK + warp;
    float* stA0 = sm + OFF_STATE + warp * STATE_STRIDE;     // pt0: 50x{h,dx,dxx,dy}
    float* stB0 = stA0 + 200;                               //      50x{dyy,dt}
    float* stA1 = stA0 + 300;                               // pt1
    float* stB1 = stA1 + 200;

    const int j1 = lane;
    const int j2 = lane + 32;
    const bool has2 = (j2 < HID);

    // ---- balanced task map: single-task warps = one per (SM, SMSP) + 48 spare.
    // Co-resident CTAs on an SM: bids {i, i+148} (classic LUT keys on bid%148).
    // nd warps: bid<148 & warp<4 (592) and bid in [148,196) & warp==4 (48).
    // All other 1728 warps take exactly one extra task -> <=7 tasks per SMSP.
    bool nd; int nd_below;
    if (bid < 148) {
        nd = (warp < 4);
        nd_below = bid * 4 + (warp < 4 ? warp : 4);
    } else {
        nd = (bid < 196) && (warp == 4);
        int below2 = (bid < 196) ? (bid - 148) : 48;
        nd_below = 592 + below2 + ((bid < 196 && warp > 4) ? 1 : 0);
    }
    const int extra = nd ? -1 : (TOTAL_WARPS + gwarp - nd_below);   // [2368,4096)

    for (int rep = 0; rep < 2; rep++) {
        int task = rep ? extra : gwarp;
        if (task < 0) break;
        const int p0 = task * 2;
        const float x00 = x[p0 * 3 + 0], x01 = x[p0 * 3 + 1], x02 = x[p0 * 3 + 2];
        const float x10 = x[p0 * 3 + 3], x11 = x[p0 * 3 + 4], x12 = x[p0 * 3 + 5];
        __syncwarp();   // prior task's epilogue reads done before overwrite

        // ---- input layer for both points
        #pragma unroll
        for (int o = 0; o < 2; o++) {
            int j = lane + 32 * o;
            if (j < HID) {
                float w0 = sm[OFF_WIN + j];
                float w1 = sm[OFF_WIN + 50 + j];
                float w2 = sm[OFF_WIN + 100 + j];
                float bj = sm[OFF_BIN + j];
                {
                    float z = bj + x00 * w0 + x01 * w1 + x02 * w2;
                    float h, s; tanh_s(z, h, s);
                    float d0 = s * w0, dd0 = -2.0f * h * d0 * w0;
                    float d1 = s * w1, dd1 = -2.0f * h * d1 * w1;
                    float d2 = s * w2;
                    ((float4*)stA0)[j] = make_float4(h, d0, dd0, d1);
                    ((float2*)stB0)[j] = make_float2(dd1, d2);
                }
                {
                    float z = bj + x10 * w0 + x11 * w1 + x12 * w2;
                    float h, s; tanh_s(z, h, s);
                    float d0 = s * w0, dd0 = -2.0f * h * d0 * w0;
                    float d1 = s * w1, dd1 = -2.0f * h * d1 * w1;
                    float d2 = s * w2;
                    ((float4*)stA1)[j] = make_float4(h, d0, dd0, d1);
                    ((float2*)stB1)[j] = make_float2(dd1, d2);
                }
            }
        }
        __syncwarp();

        // ---- 4 hidden layers: shared weight loads, 2 points, 24 FMA per k
        for (int l = 0; l < 4; l++) {
            const float* Wl = sm + OFF_WH + l * 2500;
            const float* bl = sm + OFF_BH + l * 50;
            float b1 = bl[j1], b2 = has2 ? bl[j2] : 0.0f;

            float p000 = b1, p001 = b2;
            float p010 = 0.f, p011 = 0.f, p020 = 0.f, p021 = 0.f;
            float p030 = 0.f, p031 = 0.f, p040 = 0.f, p041 = 0.f;
            float p050 = 0.f, p051 = 0.f;
            float p100 = b1, p101 = b2;
            float p110 = 0.f, p111 = 0.f, p120 = 0.f, p121 = 0.f;
            float p130 = 0.f, p131 = 0.f, p140 = 0.f, p141 = 0.f;
            float p150 = 0.f, p151 = 0.f;

            #pragma unroll
            for (int k = 0; k < HID; k++) {
                float w1 = Wl[k * 50 + j1];
                float w2 = has2 ? Wl[k * 50 + j2] : 0.0f;
                float4 A0 = ((const float4*)stA0)[k];
                float2 B0 = ((const float2*)stB0)[k];
                float4 A1 = ((const float4*)stA1)[k];
                float2 B1 = ((const float2*)stB1)[k];
                p000 = fmaf(A0.x, w1, p000); p001 = fmaf(A0.x, w2, p001);
                p010 = fmaf(A0.y, w1, p010); p011 = fmaf(A0.y, w2, p011);
                p020 = fmaf(A0.z, w1, p020); p021 = fmaf(A0.z, w2, p021);
                p030 = fmaf(A0.w, w1, p030); p031 = fmaf(A0.w, w2, p031);
                p040 = fmaf(B0.x, w1, p040); p041 = fmaf(B0.x, w2, p041);
                p050 = fmaf(B0.y, w1, p050); p051 = fmaf(B0.y, w2, p051);
                p100 = fmaf(A1.x, w1, p100); p101 = fmaf(A1.x, w2, p101);
                p110 = fmaf(A1.y, w1, p110); p111 = fmaf(A1.y, w2, p111);
                p120 = fmaf(A1.z, w1, p120); p121 = fmaf(A1.z, w2, p121);
                p130 = fmaf(A1.w, w1, p130); p131 = fmaf(A1.w, w2, p131);
                p140 = fmaf(B1.x, w1, p140); p141 = fmaf(B1.x, w2, p141);
                p150 = fmaf(B1.y, w1, p150); p151 = fmaf(B1.y, w2, p151);
            }
            __syncwarp();   // all reads of old state complete before overwrite
            chain_store(stA0, stB0, j1, p000, p010, p020, p030, p040, p050);
            chain_store(stA1, stB1, j1, p100, p110, p120, p130, p140, p150);
            if (has2) {
                chain_store(stA0, stB0, j2, p001, p011, p021, p031, p041, p051);
                chain_store(stA1, stB1, j2, p101, p111, p121, p131, p141, p151);
            }
            __syncwarp();
        }

        // ---- output layer: 8 dot products per point; lanes 0-7 pt0, 8-15 pt1
        if (lane < 16) {
            int pt = lane >> 3;
            int l8 = lane & 7;
            int cidx = l8 >> 1;              // 0=val, 1=dxx, 2=dyy, 3=dt
            int o = l8 & 1;
            float* sA = pt ? stA1 : stA0;
            float* sB = pt ? stB1 : stB0;
            const float* cp = (cidx < 2) ? (sA + 2 * cidx) : (sB + (cidx - 2));
            int cstr = (cidx < 2) ? 4 : 2;
            float acc0 = (cidx == 0) ? sm[OFF_BO + o] : 0.0f;
            float acc1 = 0.0f;
            #pragma unroll
            for (int k = 0; k < HID; k += 2) {
                acc0 = fmaf(cp[k * cstr],       sm[OFF_WO + k * 2 + o],       acc0);
                acc1 = fmaf(cp[(k + 1) * cstr], sm[OFF_WO + (k + 1) * 2 + o], acc1);
            }
            sm[OFF_OUT16 + warp * 16 + lane] = acc0 + acc1;
        }
        __syncwarp();

        if (lane < 2) {                      // lane 0 -> pt0, lane 1 -> pt1
            const float* o8 = sm + OFF_OUT16 + warp * 16 + lane * 8;
            float u   = o8[0], v   = o8[1];
            float uxx = o8[2], vxx = o8[3];
            float uyy = o8[4], vyy = o8[5];
            float ut  = o8[6], vt  = o8[7];
            float Q  = u * u + v * v;
            float A1 = vt - 0.5f * uxx - 0.5f * vyy - Q * u + v;
            float A2 = ut + 0.5f * vxx - 0.5f * uyy + Q * v + u;
            float B1 = uyy, B2 = vyy;
            float C1 = Q * v, C2 = Q * u;
            float* pp = sm + OFF_PART + (warp * 2 + lane) * 6;
            pp[0] += A1 * A1 + A2 * A2;
            pp[1] += B1 * B1 + B2 * B2;
            pp[2] += C1 * C1 + C2 * C2;
            pp[3] += A2 * B2 - A1 * B1;
            pp[4] += A1 * C1 + A2 * C2;
            pp[5] += B1 * C1 - B2 * C2;
        }
    }
    __syncthreads();

    if (tid < 6) {
        double s = 0.0;
        #pragma unroll
        for (int w = 0; w < WARPS_PER_BLOCK * 2; w++)
            s += (double)sm[OFF_PART + w * 6 + tid];
        atomicAdd(&g_sums[tid], s);
    }
    __syncthreads();

    // ---- last-block-done: fused finalize (float math; serial tail ~1-2us)
    if (tid == 0) {
        __threadfence();
        unsigned t = atomicAdd(&g_ticket, 1u);
        ((unsigned*)sm)[OFF_FLAG] = (t == (unsigned)(NBLOCKS - 1)) ? 1u : 0u;
    }
    __syncthreads();

    if (((unsigned*)sm)[OFF_FLAG]) {
        __threadfence();   // acquire: all blocks' g_sums additions visible
        float s0 = (float)*(volatile double*)&g_sums[0];
        float s1 = (float)*(volatile double*)&g_sums[1];
        float s2 = (float)*(volatile double*)&g_sums[2];
        float s3 = (float)*(volatile double*)&g_sums[3];
        float s4 = (float)*(volatile double*)&g_sums[4];
        float s5 = (float)*(volatile double*)&g_sums[5];
        for (int p = tid; p < NPARA; p += THREADS) {
            float a = para[p * 3 + 0];
            float c = para[p * 3 + 2];
            float r = s0 + 0.25f * a * a * s1 + c * c * s2
                    + a * s3 - 2.0f * c * s4 + a * c * s5;
            out[p] = r * (1.0f / (float)NPTS);
        }
        __syncthreads();
        if (tid == 0) {                 // reset for next graph replay
            g_ticket = 0u;
            #pragma unroll
            for (int i = 0; i < 6; i++) g_sums[i] = 0.0;
        }
    }
}

extern "C" void kernel_launch(void* const* d_in, const int* in_sizes, int n_in,
                              void* d_out, int out_size) {
    const float* x     = (const float*)d_in[0];
    const float* para  = (const float*)d_in[1];
    const float* W_in  = (const float*)d_in[2];
    const float* b_in  = (const float*)d_in[3];
    const float* W_hid = (const float*)d_in[4];
    const float* b_hid = (const float*)d_in[5];
    const float* W_out = (const float*)d_in[6];
    const float* b_out = (const float*)d_in[7];
    float* out = (float*)d_out;

    cudaFuncSetAttribute(pinn_kernel, cudaFuncAttributeMaxDynamicSharedMemorySize, SMEM_BYTES);
    pinn_kernel<<<NBLOCKS, THREADS, SMEM_BYTES>>>(
        x, para, W_in, b_in, W_hid, b_hid, W_out, b_out, out);
}

// round 11
// speedup vs baseline: 1.1557x; 1.1235x over previous
#include <cuda_runtime.h>

#define HID 50
#define NPTS 8192
#define NPARA 5000
#define WARPS_PER_BLOCK 8
#define THREADS (WARPS_PER_BLOCK * 32)
#define NBLOCKS 296                      // exactly 2 CTAs per SM on 148 SMs
#define TOTAL_WARPS (NBLOCKS * WARPS_PER_BLOCK)   // 2368
#define NTASKS (NPTS / 2)                // 4096 two-point tasks

// shared layout (floats)
#define OFF_WIN 0
#define OFF_BIN 150
#define OFF_WH  200
#define OFF_BH  10200
#define OFF_WO  10400
#define OFF_BO  10500
#define OFF_STATE 10504                 // 16B aligned
#define STATE_STRIDE 600                // 2 points x (stA 50x4 + stB 50x2)
#define OFF_OUT16 (OFF_STATE + WARPS_PER_BLOCK * STATE_STRIDE)  // 15304
#define OFF_PART (OFF_OUT16 + WARPS_PER_BLOCK * 16)             // 15432
#define SMEM_FLOATS (OFF_PART + WARPS_PER_BLOCK * 12)           // 15528
#define SMEM_BYTES (SMEM_FLOATS * 4)    // ~60.7 KB

typedef unsigned long long u64;

__device__ double g_sums[6];            // zero-initialized at load; reset after finalize

__device__ __forceinline__ u64 pack2(float lo, float hi) {
    u64 r; asm("mov.b64 %0, {%1, %2};" : "=l"(r) : "f"(lo), "f"(hi)); return r;
}
__device__ __forceinline__ void unpack2(u64 v, float& lo, float& hi) {
    asm("mov.b64 {%0, %1}, %2;" : "=f"(lo), "=f"(hi) : "l"(v));
}
// d.lo += a.lo*b.lo ; d.hi += a.hi*b.hi   (SASS FFMA2, PTX-only)
__device__ __forceinline__ void ffma2(u64& d, u64 a, u64 b) {
    asm("fma.rn.f32x2 %0, %1, %2, %0;" : "+l"(d) : "l"(a), "l"(b));
}

// tanh(z) and sech^2(z): r = 1/(e^{2z}+1); h = 1-2r; 1-h^2 = 4r(1-r)
__device__ __forceinline__ void tanh_s(float z, float& h, float& s) {
    float e = __expf(2.0f * z);
    float r = __fdividef(1.0f, e + 1.0f);
    h = 1.0f - 2.0f * r;
    s = 4.0f * r * (1.0f - r);
}

// tanh chain + split-array state write for one unit of one point
__device__ __forceinline__ void chain_store(float* stA, float* stB, int j,
                                            float z, float zx, float zxx,
                                            float zy, float zyy, float zt) {
    float h, s; tanh_s(z, h, s);
    float d0  = s * zx;
    float dd0 = fmaf(-2.0f * h * d0, zx, s * zxx);
    float d1  = s * zy;
    float dd1 = fmaf(-2.0f * h * d1, zy, s * zyy);
    float d2  = s * zt;
    ((float4*)stA)[j] = make_float4(h, d0, dd0, d1);
    ((float2*)stB)[j] = make_float2(dd1, d2);
}

__global__ void __launch_bounds__(THREADS) pinn_kernel(
    const float* __restrict__ x,
    const float* __restrict__ W_in, const float* __restrict__ b_in,
    const float* __restrict__ W_hid, const float* __restrict__ b_hid,
    const float* __restrict__ W_out, const float* __restrict__ b_out)
{
    extern __shared__ float sm[];
    const int tid = threadIdx.x;

    for (int i = tid; i < 2500; i += THREADS)
        ((float4*)(sm + OFF_WH))[i] = ((const float4*)W_hid)[i];
    for (int i = tid; i < 150;  i += THREADS) sm[OFF_WIN + i] = W_in[i];
    for (int i = tid; i < 50;   i += THREADS) sm[OFF_BIN + i] = b_in[i];
    for (int i = tid; i < 200;  i += THREADS) sm[OFF_BH  + i] = b_hid[i];
    for (int i = tid; i < 100;  i += THREADS) sm[OFF_WO  + i] = W_out[i];
    if (tid < 2) sm[OFF_BO + tid] = b_out[tid];
    for (int i = tid; i < WARPS_PER_BLOCK * 12; i += THREADS)
        sm[OFF_PART + i] = 0.0f;        // per-warp residual accumulators
    __syncthreads();

    const int warp = tid >> 5;
    const int lane = tid & 31;
    const int gwarp = blockIdx.x * WARPS_PER_BLOCK + warp;
    float* stA0 = sm + OFF_STATE + warp * STATE_STRIDE;     // pt0: 50x{h,dx,dxx,dy}
    float* stB0 = stA0 + 200;                               //      50x{dyy,dt}
    float* stA1 = stA0 + 300;                               // pt1
    float* stB1 = stA1 + 200;

    const int j1 = lane;
    const int j2 = lane + 32;
    const bool has2 = (j2 < HID);

    for (int task = gwarp; task < NTASKS; task += TOTAL_WARPS) {
        const int p0 = task * 2;
        const float x00 = x[p0 * 3 + 0], x01 = x[p0 * 3 + 1], x02 = x[p0 * 3 + 2];
        const float x10 = x[p0 * 3 + 3], x11 = x[p0 * 3 + 4], x12 = x[p0 * 3 + 5];
        __syncwarp();   // prior task's epilogue reads done before overwrite

        // ---- input layer for both points
        #pragma unroll
        for (int o = 0; o < 2; o++) {
            int j = lane + 32 * o;
            if (j < HID) {
                float w0 = sm[OFF_WIN + j];
                float w1 = sm[OFF_WIN + 50 + j];
                float w2 = sm[OFF_WIN + 100 + j];
                float bj = sm[OFF_BIN + j];
                {
                    float z = bj + x00 * w0 + x01 * w1 + x02 * w2;
                    float h, s; tanh_s(z, h, s);
                    float d0 = s * w0, dd0 = -2.0f * h * d0 * w0;
                    float d1 = s * w1, dd1 = -2.0f * h * d1 * w1;
                    float d2 = s * w2;
                    ((float4*)stA0)[j] = make_float4(h, d0, dd0, d1);
                    ((float2*)stB0)[j] = make_float2(dd1, d2);
                }
                {
                    float z = bj + x10 * w0 + x11 * w1 + x12 * w2;
                    float h, s; tanh_s(z, h, s);
                    float d0 = s * w0, dd0 = -2.0f * h * d0 * w0;
                    float d1 = s * w1, dd1 = -2.0f * h * d1 * w1;
                    float d2 = s * w2;
                    ((float4*)stA1)[j] = make_float4(h, d0, dd0, d1);
                    ((float2*)stB1)[j] = make_float2(dd1, d2);
                }
            }
        }
        __syncwarp();

        // ---- 4 hidden layers: identical loads to R8, arithmetic as 12 FFMA2/k
        for (int l = 0; l < 4; l++) {
            const float* Wl = sm + OFF_WH + l * 2500;
            const float* bl = sm + OFF_BH + l * 50;
            float b1 = bl[j1], b2 = has2 ? bl[j2] : 0.0f;

            // pt0: P*a (weight col j1), P*b (col j2); pt1: Q*a, Q*b
            // pair layout: {z,zx} {zxx,zy} {zyy,zt}
            u64 P0a = pack2(b1, 0.0f), P1a = 0ull, P2a = 0ull;
            u64 P0b = pack2(b2, 0.0f), P1b = 0ull, P2b = 0ull;
            u64 Q0a = pack2(b1, 0.0f), Q1a = 0ull, Q2a = 0ull;
            u64 Q0b = pack2(b2, 0.0f), Q1b = 0ull, Q2b = 0ull;

            #pragma unroll
            for (int k = 0; k < HID; k++) {
                float w1 = Wl[k * 50 + j1];                  // LDS.32, 1 wf
                float w2 = has2 ? Wl[k * 50 + j2] : 0.0f;    // LDS.32, 1 wf
                u64 ww1 = pack2(w1, w1);
                u64 ww2 = pack2(w2, w2);
                ulonglong2 A0 = ((const ulonglong2*)stA0)[k]; // LDS.128 bcast: {h,dx}{dxx,dy}
                u64        B0 = ((const u64*)stB0)[k];        // LDS.64  bcast: {dyy,dt}
                ulonglong2 A1 = ((const ulonglong2*)stA1)[k];
                u64        B1 = ((const u64*)stB1)[k];
                ffma2(P0a, A0.x, ww1); ffma2(P1a, A0.y, ww1); ffma2(P2a, B0, ww1);
                ffma2(P0b, A0.x, ww2); ffma2(P1b, A0.y, ww2); ffma2(P2b, B0, ww2);
                ffma2(Q0a, A1.x, ww1); ffma2(Q1a, A1.y, ww1); ffma2(Q2a, B1, ww1);
                ffma2(Q0b, A1.x, ww2); ffma2(Q1b, A1.y, ww2); ffma2(Q2b, B1, ww2);
            }
            __syncwarp();   // all reads of old state complete before overwrite
            {
                float z, zx, zxx, zy, zyy, zt;
                unpack2(P0a, z, zx); unpack2(P1a, zxx, zy); unpack2(P2a, zyy, zt);
                chain_store(stA0, stB0, j1, z, zx, zxx, zy, zyy, zt);
                unpack2(Q0a, z, zx); unpack2(Q1a, zxx, zy); unpack2(Q2a, zyy, zt);
                chain_store(stA1, stB1, j1, z, zx, zxx, zy, zyy, zt);
            }
            if (has2) {
                float z, zx, zxx, zy, zyy, zt;
                unpack2(P0b, z, zx); unpack2(P1b, zxx, zy); unpack2(P2b, zyy, zt);
                chain_store(stA0, stB0, j2, z, zx, zxx, zy, zyy, zt);
                unpack2(Q0b, z, zx); unpack2(Q1b, zxx, zy); unpack2(Q2b, zyy, zt);
                chain_store(stA1, stB1, j2, z, zx, zxx, zy, zyy, zt);
            }
            __syncwarp();
        }

        // ---- output layer: 8 dot products per point; lanes 0-7 pt0, 8-15 pt1
        if (lane < 16) {
            int pt = lane >> 3;
            int l8 = lane & 7;
            int cidx = l8 >> 1;              // 0=val, 1=dxx, 2=dyy, 3=dt
            int o = l8 & 1;
            float* sA = pt ? stA1 : stA0;
            float* sB = pt ? stB1 : stB0;
            const float* cp = (cidx < 2) ? (sA + 2 * cidx) : (sB + (cidx - 2));
            int cstr = (cidx < 2) ? 4 : 2;
            float acc0 = (cidx == 0) ? sm[OFF_BO + o] : 0.0f;
            float acc1 = 0.0f;
            #pragma unroll
            for (int k = 0; k < HID; k += 2) {
                acc0 = fmaf(cp[k * cstr],       sm[OFF_WO + k * 2 + o],       acc0);
                acc1 = fmaf(cp[(k + 1) * cstr], sm[OFF_WO + (k + 1) * 2 + o], acc1);
            }
            sm[OFF_OUT16 + warp * 16 + lane] = acc0 + acc1;
        }
        __syncwarp();

        if (lane < 2) {                      // lane 0 -> pt0, lane 1 -> pt1
            const float* o8 = sm + OFF_OUT16 + warp * 16 + lane * 8;
            float u   = o8[0], v   = o8[1];
            float uxx = o8[2], vxx = o8[3];
            float uyy = o8[4], vyy = o8[5];
            float ut  = o8[6], vt  = o8[7];
            float Q  = u * u + v * v;
            float A1 = vt - 0.5f * uxx - 0.5f * vyy - Q * u + v;
            float A2 = ut + 0.5f * vxx - 0.5f * uyy + Q * v + u;
            float B1 = uyy, B2 = vyy;
            float C1 = Q * v, C2 = Q * u;
            float* pp = sm + OFF_PART + (warp * 2 + lane) * 6;
            pp[0] += A1 * A1 + A2 * A2;
            pp[1] += B1 * B1 + B2 * B2;
            pp[2] += C1 * C1 + C2 * C2;
            pp[3] += A2 * B2 - A1 * B1;
            pp[4] += A1 * C1 + A2 * C2;
            pp[5] += B1 * C1 - B2 * C2;
        }
    }
    __syncthreads();

    if (tid < 6) {
        double s = 0.0;
        #pragma unroll
        for (int w = 0; w < WARPS_PER_BLOCK * 2; w++)
            s += (double)sm[OFF_PART + w * 6 + tid];
        atomicAdd(&g_sums[tid], s);
    }
}

__global__ void finalize_kernel(const float* __restrict__ para, float* __restrict__ out) {
    int p = blockIdx.x * blockDim.x + threadIdx.x;
    if (p < NPARA) {
        double a = (double)para[p * 3 + 0];
        double c = (double)para[p * 3 + 2];
        double r = g_sums[0]
                 + 0.25 * a * a * g_sums[1]
                 + c * c * g_sums[2]
                 + a * g_sums[3]
                 - 2.0 * c * g_sums[4]
                 + a * c * g_sums[5];
        out[p] = (float)(r * (1.0 / (double)NPTS));
    }
}

__global__ void reset_kernel() {
    if (threadIdx.x < 6) g_sums[threadIdx.x] = 0.0;
}

extern "C" void kernel_launch(void* const* d_in, const int* in_sizes, int n_in,
                              void* d_out, int out_size) {
    const float* x     = (const float*)d_in[0];
    const float* para  = (const float*)d_in[1];
    const float* W_in  = (const float*)d_in[2];
    const float* b_in  = (const float*)d_in[3];
    const float* W_hid = (const float*)d_in[4];
    const float* b_hid = (const float*)d_in[5];
    const float* W_out = (const float*)d_in[6];
    const float* b_out = (const float*)d_in[7];
    float* out = (float*)d_out;

    cudaFuncSetAttribute(pinn_kernel, cudaFuncAttributeMaxDynamicSharedMemorySize, SMEM_BYTES);
    pinn_kernel<<<NBLOCKS, THREADS, SMEM_BYTES>>>(
        x, W_in, b_in, W_hid, b_hid, W_out, b_out);
    finalize_kernel<<<(NPARA + 255) / 256, 256>>>(para, out);
    reset_kernel<<<1, 32>>>();
}